// round 13
// baseline (speedup 1.0000x reference)
#include <cuda_runtime.h>
#include <math.h>

#define N_PTS 8192
#define CH    1024
#define HH    128
#define WW    128
#define WP    130           // padded width/height for zero-pad Sobel window
#define GRID_A 1024
#define BLOCK_A 256
#define NWARP  (BLOCK_A/32)
#define NCOMP 28            // 6 g + 21 Hs + 1 cost
#define ITERS 10
#define SPAD 132            // smem pixel pad for transpose tile

// ---------------- device scratch (static: allocation-free) ----------------
__device__ float g_qt[WP*WP*CH];      // padded transposed query feat (border stays 0)
__device__ float g_feat0[N_PTS*CH];   // reference features per point
__device__ float g_pts0[N_PTS*3];
__device__ float g_state[40];         // 0-8 R, 9-11 t, 12 lam, 13 prev, 14-22 Rn, 23-25 tn, 26 nanflag
__device__ float g_partial[NCOMP*GRID_A];
__device__ float g_ncost_part[GRID_A];

__constant__ int cPI[21] = {0,0,0,0,0,0, 1,1,1,1,1, 2,2,2,2, 3,3,3, 4,4, 5};
__constant__ int cPJ[21] = {0,1,2,3,4,5, 1,2,3,4,5, 2,3,4,5, 3,4,5, 4,5, 5};

__device__ __forceinline__ void grid_dep_wait() {
    asm volatile("griddepcontrol.wait;" ::: "memory");
}
__device__ __forceinline__ float decode_sr(const void* p) {
    int iv = *(const int*)p;
    if (iv >= 1 && iv <= 4096) return (float)iv;
    return *(const float*)p;
}
__device__ __forceinline__ int clampi(int v, int lo, int hi) {
    return v < lo ? lo : (v > hi ? hi : v);
}
__device__ __forceinline__ float4 LD4(const float* p) {
    return *reinterpret_cast<const float4*>(p);
}

// ---------------- setup kernels (mutually independent; overlap via PDL) ----------------
__global__ void k_init(const float* q, const float* r) {
    if (threadIdx.x != 0 || blockIdx.x != 0) return;
    double a[4][8];
    for (int i = 0; i < 4; i++)
        for (int j = 0; j < 4; j++) { a[i][j] = r[i*4+j]; a[i][4+j] = (i == j) ? 1.0 : 0.0; }
    for (int col = 0; col < 4; col++) {
        int piv = col; double best = fabs(a[col][col]);
        for (int rr = col+1; rr < 4; rr++) if (fabs(a[rr][col]) > best) { best = fabs(a[rr][col]); piv = rr; }
        if (piv != col) for (int j = 0; j < 8; j++) { double tmp = a[col][j]; a[col][j] = a[piv][j]; a[piv][j] = tmp; }
        double d = a[col][col];
        for (int j = 0; j < 8; j++) a[col][j] /= d;
        for (int rr = 0; rr < 4; rr++) if (rr != col) {
            double f = a[rr][col];
            for (int j = 0; j < 8; j++) a[rr][j] -= f * a[col][j];
        }
    }
    double rel[4][4];
    for (int i = 0; i < 4; i++)
        for (int j = 0; j < 4; j++) {
            double s = 0;
            for (int k = 0; k < 4; k++) s += (double)q[i*4+k] * a[k][4+j];
            rel[i][j] = s;
        }
    for (int i = 0; i < 3; i++)
        for (int j = 0; j < 3; j++) g_state[i*3+j] = (float)rel[i][j];
    g_state[9]  = (float)rel[3][0];
    g_state[10] = (float)rel[3][1];
    g_state[11] = (float)rel[3][2];
    g_state[12] = 0.01f;                         // lambda
    g_state[13] = __int_as_float(0x7f800000);    // prev = +inf
    g_state[26] = 0.f;
}

__global__ void k_pts0(const float* p3d, const float* r) {
    int i = blockIdx.x * blockDim.x + threadIdx.x;
    if (i >= N_PTS) return;
    float ph[4] = { p3d[3*i], p3d[3*i+1], p3d[3*i+2], 1.f };
    float v[4];
    #pragma unroll
    for (int j = 0; j < 4; j++) {
        v[j] = ph[0]*r[j*4+0] + ph[1]*r[j*4+1] + ph[2]*r[j*4+2] + ph[3]*r[j*4+3];
    }
    float inv = 1.f / v[3];
    g_pts0[3*i+0] = v[0] * inv;
    g_pts0[3*i+1] = v[1] * inv;
    g_pts0[3*i+2] = v[2] * inv;
}

// vectorized transpose (C, P=H*W) -> padded pixel-major (130x130, C)
__global__ void __launch_bounds__(256) k_transpose_q(const float* __restrict__ src) {
    __shared__ float tile[32][SPAD];
    int p0 = blockIdx.x * 128;
    int c0 = blockIdx.y * 32;
    int lane = threadIdx.x & 31;
    int w    = threadIdx.x >> 5;
    #pragma unroll
    for (int s = 0; s < 4; s++) {
        int c = w*4 + s;
        float4 v = LD4(src + (size_t)(c0 + c) * (HH*WW) + p0 + lane*4);
        *reinterpret_cast<float4*>(&tile[c][lane*4]) = v;
    }
    __syncthreads();
    int pl = w*16 + (lane >> 1);
    int p  = p0 + pl;
    int y = p >> 7, x = p & 127;
    size_t opix = (size_t)(y+1)*WP + (x+1);
    float* dp = g_qt + opix*CH + c0;
    #pragma unroll
    for (int k = 0; k < 4; k++) {
        int c = (lane & 1)*4 + 8*k;
        float4 v = make_float4(tile[c][pl], tile[c+1][pl], tile[c+2][pl], tile[c+3][pl]);
        *reinterpret_cast<float4*>(dp + c) = v;
    }
}

// gather reference features for each point directly from (C,H,W) layout
__global__ void k_feat0(const float* __restrict__ p2d, const float* __restrict__ rf, const void* srp) {
    float sr = decode_sr(srp);
    int p = blockIdx.x;
    float u = p2d[2*p], v = p2d[2*p+1];
    int ix = clampi((int)floorf(u / sr), 0, WW-1);
    int iy = clampi((int)floorf(v / sr), 0, HH-1);
    int pix = iy*WW + ix;
    #pragma unroll
    for (int c = threadIdx.x; c < CH; c += 256)
        g_feat0[(size_t)p*CH + c] = rf[(size_t)c*(HH*WW) + pix];
}

// ---------------- main per-iteration kernel (gather + J reduction) ----------------
__global__ void __launch_bounds__(BLOCK_A) k_main(const float* __restrict__ K1, const void* srp) {
    grid_dep_wait();   // PDL: wait on predecessor (k_accept / setup) before reading g_state
    float sr = decode_sr(srp);
    int lane = threadIdx.x & 31;
    int wl   = threadIdx.x >> 5;
    int p    = blockIdx.x * NWARP + wl;   // one point per warp
    __shared__ float sM[NWARP][12];
    __shared__ float comb[NWARP][NCOMP];

    float R[9], t0, t1, t2;
    #pragma unroll
    for (int i = 0; i < 9; i++) R[i] = g_state[i];
    t0 = g_state[9]; t1 = g_state[10]; t2 = g_state[11];
    float K00=K1[0],K01=K1[1],K02=K1[2],K10=K1[3],K11=K1[4],K12=K1[5],K20=K1[6],K21=K1[7],K22=K1[8];
    float fx = K00, fy = K11;

    float Px = g_pts0[3*p], Py = g_pts0[3*p+1], Pz = g_pts0[3*p+2];
    float x1 = Px*R[0] + Py*R[3] + Pz*R[6] + t0;
    float y1 = Px*R[1] + Py*R[4] + Pz*R[7] + t1;
    float z1 = Px*R[2] + Py*R[5] + Pz*R[8] + t2;
    float h0 = K00*x1 + K01*y1 + K02*z1;
    float h1 = K10*x1 + K11*y1 + K12*z1;
    float h2 = K20*x1 + K21*y1 + K22*z1;
    float ih2 = 1.f / h2;
    int ix = clampi((int)floorf(h0*ih2 / sr), 0, WW-1);
    int iy = clampi((int)floorf(h1*ih2 / sr), 0, HH-1);

    const float* base = g_qt + ((size_t)iy*WP + ix) * CH;  // top-left of padded 3x3 window
    const float* f0p  = g_feat0 + (size_t)p * CH;

    float4 c4  = make_float4(0,0,0,0);
    float4 ax4 = c4, ay4 = c4, bxx4 = c4, bxy4 = c4, byy4 = c4;
    #pragma unroll
    for (int k = 0; k < 8; k++) {
        int c = lane*4 + k*128;
        float4 w00 = LD4(base + c);
        float4 w01 = LD4(base + CH + c);
        float4 w02 = LD4(base + 2*CH + c);
        float4 w10 = LD4(base + WP*CH + c);
        float4 w11 = LD4(base + WP*CH + CH + c);
        float4 w12 = LD4(base + WP*CH + 2*CH + c);
        float4 w20 = LD4(base + 2*WP*CH + c);
        float4 w21 = LD4(base + 2*WP*CH + CH + c);
        float4 w22 = LD4(base + 2*WP*CH + 2*CH + c);
        float4 f0  = LD4(f0p + c);
        #define DO(comp) { \
            float gx = (w02.comp - w00.comp) + 2.f*(w12.comp - w10.comp) + (w22.comp - w20.comp); \
            float gy = (w20.comp - w00.comp) + 2.f*(w21.comp - w01.comp) + (w22.comp - w02.comp); \
            float er = w11.comp - f0.comp; \
            c4.comp   += er*er;  ax4.comp  += gx*er;  ay4.comp  += gy*er; \
            bxx4.comp += gx*gx;  bxy4.comp += gx*gy;  byy4.comp += gy*gy; }
        DO(x) DO(y) DO(z) DO(w)
        #undef DO
    }
    float cost = (c4.x + c4.y) + (c4.z + c4.w);
    float ax   = (ax4.x + ax4.y) + (ax4.z + ax4.w);
    float ay   = (ay4.x + ay4.y) + (ay4.z + ay4.w);
    float bxx  = (bxx4.x + bxx4.y) + (bxx4.z + bxx4.w);
    float bxy  = (bxy4.x + bxy4.y) + (bxy4.z + bxy4.w);
    float byy  = (byy4.x + byy4.y) + (byy4.z + byy4.w);
    #pragma unroll
    for (int o = 16; o > 0; o >>= 1) {
        cost += __shfl_xor_sync(0xffffffffu, cost, o);
        ax   += __shfl_xor_sync(0xffffffffu, ax, o);
        ay   += __shfl_xor_sync(0xffffffffu, ay, o);
        bxx  += __shfl_xor_sync(0xffffffffu, bxx, o);
        bxy  += __shfl_xor_sync(0xffffffffu, bxy, o);
        byy  += __shfl_xor_sync(0xffffffffu, byy, o);
    }
    if (lane == 0) {
        float iz = 1.f / z1;
        float isr = 1.f / sr;
        float Jh00 = fx * iz * isr;
        float Jh02 = -fx * x1 * iz * iz * isr;
        float Jh11 = fy * iz * isr;
        float Jh12 = -fy * y1 * iz * iz * isr;
        sM[wl][0] = Jh00;  sM[wl][1] = 0.f;  sM[wl][2] = Jh02;
        sM[wl][3] = Jh02*y1;  sM[wl][4] = Jh00*z1 - Jh02*x1;  sM[wl][5] = -Jh00*y1;
        sM[wl][6] = 0.f;  sM[wl][7] = Jh11;  sM[wl][8] = Jh12;
        sM[wl][9] = Jh12*y1 - Jh11*z1;  sM[wl][10] = -Jh12*x1;  sM[wl][11] = Jh11*x1;
    }
    __syncwarp();
    float acc = 0.f;
    if (lane < 6) {
        acc = ax * sM[wl][lane] + ay * sM[wl][6+lane];
    } else if (lane < 27) {
        int q = lane - 6;
        int i = cPI[q], j = cPJ[q];
        float m0i = sM[wl][i],   m1i = sM[wl][6+i];
        float m0j = sM[wl][j],   m1j = sM[wl][6+j];
        acc = bxx*m0i*m0j + bxy*(m0i*m1j + m0j*m1i) + byy*m1i*m1j;
    } else if (lane == 27) {
        acc = cost;
    }
    if (lane < NCOMP) comb[wl][lane] = acc;
    __syncthreads();
    if (threadIdx.x < NCOMP) {
        float s = 0.f;
        #pragma unroll
        for (int w = 0; w < NWARP; w++) s += comb[w][threadIdx.x];
        g_partial[threadIdx.x * GRID_A + blockIdx.x] = s;
    }
}

// ---------------- reduce + 6x6 LM solve + so3 exp (single block, float32 like reference) ----------
__global__ void k_solve(int iter) {
    grid_dep_wait();   // PDL: wait for k_main's g_partial
    __shared__ float red[NCOMP][8];
    __shared__ float allv[NCOMP];
    int tid = threadIdx.x;
    if (tid < NCOMP * 8) {
        int k = tid >> 3, seg = tid & 7;
        float s = 0.f;
        for (int j = 0; j < GRID_A/8; j++) s += g_partial[k*GRID_A + seg*(GRID_A/8) + j];
        red[k][seg] = s;
    }
    __syncthreads();
    if (tid < NCOMP) {
        float s = 0.f;
        #pragma unroll
        for (int j = 0; j < 8; j++) s += red[tid][j];
        allv[tid] = s;
    }
    __syncthreads();
    if (tid != 0) return;

    float g[6];
    for (int i = 0; i < 6; i++) g[i] = allv[i];
    float Hs[6][6];
    for (int q = 0; q < 21; q++) { Hs[cPI[q]][cPJ[q]] = allv[6+q]; Hs[cPJ[q]][cPI[q]] = allv[6+q]; }
    float costsum = allv[27];
    float lam = g_state[12];
    float prev = g_state[13];
    if (iter == 0) prev = costsum / (float)N_PTS;

    float A[6][7];
    for (int i = 0; i < 6; i++) {
        for (int j = 0; j < 6; j++) A[i][j] = Hs[i][j];
        A[i][i] += (Hs[i][i] + 1e-9f) * lam;
        A[i][6] = g[i];
    }
    for (int col = 0; col < 6; col++) {
        int piv = col; float best = fabsf(A[col][col]);
        for (int rr = col+1; rr < 6; rr++) if (fabsf(A[rr][col]) > best) { best = fabsf(A[rr][col]); piv = rr; }
        if (piv != col) for (int j = 0; j < 7; j++) { float tmp = A[col][j]; A[col][j] = A[piv][j]; A[piv][j] = tmp; }
        float d = A[col][col];
        for (int rr = col+1; rr < 6; rr++) {
            float f = A[rr][col] / d;
            for (int j = col; j < 7; j++) A[rr][j] -= f * A[col][j];
        }
    }
    float xs[6];
    for (int i = 5; i >= 0; i--) {
        float s = A[i][6];
        for (int j = i+1; j < 6; j++) s -= A[i][j] * xs[j];
        xs[i] = s / A[i][i];
    }
    float delta[6];
    int nanf = 0;
    for (int i = 0; i < 6; i++) { delta[i] = -xs[i]; if (isnan(delta[i])) nanf = 1; }

    float dw0 = delta[3], dw1 = delta[4], dw2 = delta[5];
    float th2 = dw0*dw0 + dw1*dw1 + dw2*dw2 + 1e-12f;
    float th = sqrtf(th2);
    float Aa = sinf(th) / th;
    float Bb = (1.0f - cosf(th)) / th2;
    float Wm[3][3] = { {0,-dw2,dw1}, {dw2,0,-dw0}, {-dw1,dw0,0} };
    float W2[3][3];
    for (int i = 0; i < 3; i++)
        for (int j = 0; j < 3; j++) {
            float s = 0;
            for (int k = 0; k < 3; k++) s += Wm[i][k]*Wm[k][j];
            W2[i][j] = s;
        }
    float dr[3][3];
    for (int i = 0; i < 3; i++)
        for (int j = 0; j < 3; j++)
            dr[i][j] = (i == j ? 1.0f : 0.0f) + Aa*Wm[i][j] + Bb*W2[i][j];

    float Rd[3][3], td[3];
    for (int i = 0; i < 3; i++) { for (int j = 0; j < 3; j++) Rd[i][j] = g_state[i*3+j]; td[i] = g_state[9+i]; }
    for (int i = 0; i < 3; i++) {
        for (int j = 0; j < 3; j++) {
            float s = 0;
            for (int k = 0; k < 3; k++) s += dr[i][k]*Rd[k][j];
            g_state[14 + i*3 + j] = s;
        }
        float s = 0;
        for (int k = 0; k < 3; k++) s += dr[i][k]*td[k];
        g_state[23+i] = s + delta[i];
    }
    g_state[26] = (float)nanf;
    g_state[13] = prev;
}

// ---------------- candidate cost evaluation ----------------
__global__ void __launch_bounds__(BLOCK_A) k_cand(const float* __restrict__ K1, const void* srp) {
    grid_dep_wait();   // PDL: wait for k_solve's candidate state
    float sr = decode_sr(srp);
    int lane = threadIdx.x & 31;
    int wl   = threadIdx.x >> 5;
    int p    = blockIdx.x * NWARP + wl;
    __shared__ float s8[NWARP];

    float Rn[9], tn0, tn1, tn2;
    #pragma unroll
    for (int i = 0; i < 9; i++) Rn[i] = g_state[14+i];
    tn0 = g_state[23]; tn1 = g_state[24]; tn2 = g_state[25];
    float K00=K1[0],K01=K1[1],K02=K1[2],K10=K1[3],K11=K1[4],K12=K1[5],K20=K1[6],K21=K1[7],K22=K1[8];

    float Px = g_pts0[3*p], Py = g_pts0[3*p+1], Pz = g_pts0[3*p+2];
    float x = Px*Rn[0] + Py*Rn[1] + Pz*Rn[2] + tn0;
    float y = Px*Rn[3] + Py*Rn[4] + Pz*Rn[5] + tn1;
    float z = Px*Rn[6] + Py*Rn[7] + Pz*Rn[8] + tn2;
    float h0 = K00*x + K01*y + K02*z;
    float h1 = K10*x + K11*y + K12*z;
    float h2 = K20*x + K21*y + K22*z;
    float ih2 = 1.f / h2;
    int jx = clampi((int)floorf(h0*ih2 / sr), 0, WW-1);
    int jy = clampi((int)floorf(h1*ih2 / sr), 0, HH-1);
    const float* cen = g_qt + ((size_t)(jy+1)*WP + (jx+1)) * CH;
    const float* f0p = g_feat0 + (size_t)p * CH;
    float nc = 0.f;
    #pragma unroll
    for (int k = 0; k < 8; k++) {
        int c = lane*4 + k*128;
        float4 q4 = LD4(cen + c);
        float4 f4 = LD4(f0p + c);
        float ex = q4.x - f4.x, ey = q4.y - f4.y, ez = q4.z - f4.z, ew = q4.w - f4.w;
        nc += (ex*ex + ey*ey) + (ez*ez + ew*ew);
    }
    #pragma unroll
    for (int o = 16; o > 0; o >>= 1) nc += __shfl_xor_sync(0xffffffffu, nc, o);
    if (lane == 0) s8[wl] = nc;
    __syncthreads();
    if (threadIdx.x == 0) {
        float tot = 0.f;
        #pragma unroll
        for (int w = 0; w < NWARP; w++) tot += s8[w];
        g_ncost_part[blockIdx.x] = tot;
    }
}

// ---------------- accept / reject ----------------
__global__ void k_accept() {
    grid_dep_wait();   // PDL: wait for k_cand's g_ncost_part
    int lane = threadIdx.x;
    float s = 0.f;
    for (int j = 0; j < GRID_A/32; j++) s += g_ncost_part[lane*(GRID_A/32) + j];
    #pragma unroll
    for (int o = 16; o > 0; o >>= 1) s += __shfl_xor_sync(0xffffffffu, s, o);
    if (lane == 0) {
        float ncost = s / (float)N_PTS;
        float prev = g_state[13];
        float lam  = g_state[12];
        bool nanf  = g_state[26] != 0.f;
        bool bad   = isnan(ncost) || nanf;
        bool worse = ncost > prev;
        float lu = lam * (worse ? 10.f : 0.1f);
        lu = fminf(fmaxf(lu, 1e-6f), 100.f);
        lam = bad ? lam : lu;
        bool accept = !(worse || bad);
        if (accept) {
            #pragma unroll
            for (int i = 0; i < 9; i++) g_state[i] = g_state[14+i];
            g_state[9]  = g_state[23];
            g_state[10] = g_state[24];
            g_state[11] = g_state[25];
            g_state[13] = ncost;
        }
        g_state[12] = lam;
    }
}

__global__ void k_out(float* out, int out_size) {
    int t = threadIdx.x;
    if (t < 12 && t < out_size) out[t] = g_state[t];  // R row-major then t
}

// ---------------- host launcher ----------------
extern "C" void kernel_launch(void* const* d_in, const int* in_sizes, int n_in,
                              void* d_out, int out_size) {
    const float* q   = (const float*)d_in[0];
    const float* r   = (const float*)d_in[1];
    const float* p2d = (const float*)d_in[2];
    const float* p3d = (const float*)d_in[3];
    const float* qf  = (const float*)d_in[4];
    const float* rf  = (const float*)d_in[5];
    const float* K1  = (const float*)d_in[6];
    const void*  srp = (const void*)d_in[7];
    float* out = (float*)d_out;

    cudaLaunchAttribute pss;
    pss.id = cudaLaunchAttributeProgrammaticStreamSerialization;
    pss.val.programmaticStreamSerializationAllowed = 1;

    // setup: all four kernels are mutually independent -> PSS lets them overlap
    k_init<<<1, 32>>>(q, r);
    {
        cudaLaunchConfig_t c = {};
        c.gridDim = dim3(N_PTS/256); c.blockDim = dim3(256);
        c.attrs = &pss; c.numAttrs = 1;
        cudaLaunchKernelEx(&c, k_pts0, p3d, r);
    }
    {
        cudaLaunchConfig_t c = {};
        c.gridDim = dim3(HH*WW/128, CH/32); c.blockDim = dim3(256);
        c.attrs = &pss; c.numAttrs = 1;
        cudaLaunchKernelEx(&c, k_transpose_q, qf);
    }
    {
        cudaLaunchConfig_t c = {};
        c.gridDim = dim3(N_PTS); c.blockDim = dim3(256);
        c.attrs = &pss; c.numAttrs = 1;
        cudaLaunchKernelEx(&c, k_feat0, p2d, rf, srp);
    }

    for (int it = 0; it < ITERS; it++) {
        if (it == 0) {
            // plain launch: fully serializes against ALL setup kernels
            k_main<<<GRID_A, BLOCK_A>>>(K1, srp);
        } else {
            cudaLaunchConfig_t c = {};
            c.gridDim = dim3(GRID_A); c.blockDim = dim3(BLOCK_A);
            c.attrs = &pss; c.numAttrs = 1;
            cudaLaunchKernelEx(&c, k_main, K1, srp);
        }
        {
            cudaLaunchConfig_t c = {};
            c.gridDim = dim3(1); c.blockDim = dim3(256);
            c.attrs = &pss; c.numAttrs = 1;
            cudaLaunchKernelEx(&c, k_solve, it);
        }
        {
            cudaLaunchConfig_t c = {};
            c.gridDim = dim3(GRID_A); c.blockDim = dim3(BLOCK_A);
            c.attrs = &pss; c.numAttrs = 1;
            cudaLaunchKernelEx(&c, k_cand, K1, srp);
        }
        {
            cudaLaunchConfig_t c = {};
            c.gridDim = dim3(1); c.blockDim = dim3(32);
            c.attrs = &pss; c.numAttrs = 1;
            cudaLaunchKernelEx(&c, k_accept);
        }
    }
    k_out<<<1, 32>>>(out, out_size);   // plain launch: full serialization before output
}

// round 14
// speedup vs baseline: 1.0111x; 1.0111x over previous
#include <cuda_runtime.h>
#include <math.h>

#define N_PTS 8192
#define CH    1024
#define HH    128
#define WW    128
#define WP    130           // padded width/height for zero-pad Sobel window
#define GRID_A 1024
#define BLOCK_A 256
#define NWARP  (BLOCK_A/32)
#define NCOMP 28            // 6 g + 21 Hs + 1 cost
#define ITERS 10
#define SPAD 132            // smem pixel pad for transpose tile

// ---------------- device scratch (static: allocation-free) ----------------
__device__ float g_qt[WP*WP*CH];      // padded transposed query feat (border stays 0)
__device__ float g_feat0[N_PTS*CH];   // reference features per point
__device__ float g_pts0[N_PTS*3];
__device__ float g_state[40];         // 0-8 R, 9-11 t, 12 lam, 13 prev, 14-22 Rn, 23-25 tn, 26 nanflag
__device__ float g_partial[NCOMP*GRID_A];
__device__ float g_ncost_part[GRID_A];

__constant__ int cPI[21] = {0,0,0,0,0,0, 1,1,1,1,1, 2,2,2,2, 3,3,3, 4,4, 5};
__constant__ int cPJ[21] = {0,1,2,3,4,5, 1,2,3,4,5, 2,3,4,5, 3,4,5, 4,5, 5};

__device__ __forceinline__ void grid_dep_wait() {
    asm volatile("griddepcontrol.wait;" ::: "memory");
}
__device__ __forceinline__ void grid_dep_trigger() {
    asm volatile("griddepcontrol.launch_dependents;" ::: "memory");
}
__device__ __forceinline__ float decode_sr(const void* p) {
    int iv = *(const int*)p;
    if (iv >= 1 && iv <= 4096) return (float)iv;
    return *(const float*)p;
}
__device__ __forceinline__ int clampi(int v, int lo, int hi) {
    return v < lo ? lo : (v > hi ? hi : v);
}
__device__ __forceinline__ float4 LD4(const float* p) {
    return *reinterpret_cast<const float4*>(p);
}

// ---------------- setup kernels (mutually independent; overlap via PDL) ----------------
__global__ void k_init(const float* q, const float* r) {
    if (threadIdx.x != 0 || blockIdx.x != 0) return;
    double a[4][8];
    for (int i = 0; i < 4; i++)
        for (int j = 0; j < 4; j++) { a[i][j] = r[i*4+j]; a[i][4+j] = (i == j) ? 1.0 : 0.0; }
    for (int col = 0; col < 4; col++) {
        int piv = col; double best = fabs(a[col][col]);
        for (int rr = col+1; rr < 4; rr++) if (fabs(a[rr][col]) > best) { best = fabs(a[rr][col]); piv = rr; }
        if (piv != col) for (int j = 0; j < 8; j++) { double tmp = a[col][j]; a[col][j] = a[piv][j]; a[piv][j] = tmp; }
        double d = a[col][col];
        for (int j = 0; j < 8; j++) a[col][j] /= d;
        for (int rr = 0; rr < 4; rr++) if (rr != col) {
            double f = a[rr][col];
            for (int j = 0; j < 8; j++) a[rr][j] -= f * a[col][j];
        }
    }
    double rel[4][4];
    for (int i = 0; i < 4; i++)
        for (int j = 0; j < 4; j++) {
            double s = 0;
            for (int k = 0; k < 4; k++) s += (double)q[i*4+k] * a[k][4+j];
            rel[i][j] = s;
        }
    for (int i = 0; i < 3; i++)
        for (int j = 0; j < 3; j++) g_state[i*3+j] = (float)rel[i][j];
    g_state[9]  = (float)rel[3][0];
    g_state[10] = (float)rel[3][1];
    g_state[11] = (float)rel[3][2];
    g_state[12] = 0.01f;                         // lambda
    g_state[13] = __int_as_float(0x7f800000);    // prev = +inf
    g_state[26] = 0.f;
}

__global__ void k_pts0(const float* p3d, const float* r) {
    int i = blockIdx.x * blockDim.x + threadIdx.x;
    if (i >= N_PTS) return;
    float ph[4] = { p3d[3*i], p3d[3*i+1], p3d[3*i+2], 1.f };
    float v[4];
    #pragma unroll
    for (int j = 0; j < 4; j++) {
        v[j] = ph[0]*r[j*4+0] + ph[1]*r[j*4+1] + ph[2]*r[j*4+2] + ph[3]*r[j*4+3];
    }
    float inv = 1.f / v[3];
    g_pts0[3*i+0] = v[0] * inv;
    g_pts0[3*i+1] = v[1] * inv;
    g_pts0[3*i+2] = v[2] * inv;
}

// vectorized transpose (C, P=H*W) -> padded pixel-major (130x130, C)
__global__ void __launch_bounds__(256) k_transpose_q(const float* __restrict__ src) {
    __shared__ float tile[32][SPAD];
    int p0 = blockIdx.x * 128;
    int c0 = blockIdx.y * 32;
    int lane = threadIdx.x & 31;
    int w    = threadIdx.x >> 5;
    #pragma unroll
    for (int s = 0; s < 4; s++) {
        int c = w*4 + s;
        float4 v = LD4(src + (size_t)(c0 + c) * (HH*WW) + p0 + lane*4);
        *reinterpret_cast<float4*>(&tile[c][lane*4]) = v;
    }
    __syncthreads();
    int pl = w*16 + (lane >> 1);
    int p  = p0 + pl;
    int y = p >> 7, x = p & 127;
    size_t opix = (size_t)(y+1)*WP + (x+1);
    float* dp = g_qt + opix*CH + c0;
    #pragma unroll
    for (int k = 0; k < 4; k++) {
        int c = (lane & 1)*4 + 8*k;
        float4 v = make_float4(tile[c][pl], tile[c+1][pl], tile[c+2][pl], tile[c+3][pl]);
        *reinterpret_cast<float4*>(dp + c) = v;
    }
}

// gather reference features for each point directly from (C,H,W) layout
__global__ void k_feat0(const float* __restrict__ p2d, const float* __restrict__ rf, const void* srp) {
    float sr = decode_sr(srp);
    int p = blockIdx.x;
    float u = p2d[2*p], v = p2d[2*p+1];
    int ix = clampi((int)floorf(u / sr), 0, WW-1);
    int iy = clampi((int)floorf(v / sr), 0, HH-1);
    int pix = iy*WW + ix;
    #pragma unroll
    for (int c = threadIdx.x; c < CH; c += 256)
        g_feat0[(size_t)p*CH + c] = rf[(size_t)c*(HH*WW) + pix];
}

// ---------------- main per-iteration kernel (gather + J reduction) ----------------
__global__ void __launch_bounds__(BLOCK_A) k_main(const float* __restrict__ K1, const void* srp) {
    float sr = decode_sr(srp);
    int lane = threadIdx.x & 31;
    int wl   = threadIdx.x >> 5;
    int p    = blockIdx.x * NWARP + wl;   // one point per warp
    __shared__ float sM[NWARP][12];
    __shared__ float comb[NWARP][NCOMP];

    // iteration-invariant loads: overlap with predecessor drain (before the PDL wait)
    float Px = g_pts0[3*p], Py = g_pts0[3*p+1], Pz = g_pts0[3*p+2];
    float K00=K1[0],K01=K1[1],K02=K1[2],K10=K1[3],K11=K1[4],K12=K1[5],K20=K1[6],K21=K1[7],K22=K1[8];
    float fx = K00, fy = K11;

    grid_dep_wait();   // PDL: wait on predecessor (k_accept / setup) before reading g_state

    float R[9], t0, t1, t2;
    #pragma unroll
    for (int i = 0; i < 9; i++) R[i] = g_state[i];
    t0 = g_state[9]; t1 = g_state[10]; t2 = g_state[11];

    float x1 = Px*R[0] + Py*R[3] + Pz*R[6] + t0;
    float y1 = Px*R[1] + Py*R[4] + Pz*R[7] + t1;
    float z1 = Px*R[2] + Py*R[5] + Pz*R[8] + t2;
    float h0 = K00*x1 + K01*y1 + K02*z1;
    float h1 = K10*x1 + K11*y1 + K12*z1;
    float h2 = K20*x1 + K21*y1 + K22*z1;
    float ih2 = 1.f / h2;
    int ix = clampi((int)floorf(h0*ih2 / sr), 0, WW-1);
    int iy = clampi((int)floorf(h1*ih2 / sr), 0, HH-1);

    const float* base = g_qt + ((size_t)iy*WP + ix) * CH;  // top-left of padded 3x3 window
    const float* f0p  = g_feat0 + (size_t)p * CH;

    float4 c4  = make_float4(0,0,0,0);
    float4 ax4 = c4, ay4 = c4, bxx4 = c4, bxy4 = c4, byy4 = c4;
    #pragma unroll
    for (int k = 0; k < 8; k++) {
        int c = lane*4 + k*128;
        float4 w00 = LD4(base + c);
        float4 w01 = LD4(base + CH + c);
        float4 w02 = LD4(base + 2*CH + c);
        float4 w10 = LD4(base + WP*CH + c);
        float4 w11 = LD4(base + WP*CH + CH + c);
        float4 w12 = LD4(base + WP*CH + 2*CH + c);
        float4 w20 = LD4(base + 2*WP*CH + c);
        float4 w21 = LD4(base + 2*WP*CH + CH + c);
        float4 w22 = LD4(base + 2*WP*CH + 2*CH + c);
        float4 f0  = LD4(f0p + c);
        #define DO(comp) { \
            float gx = (w02.comp - w00.comp) + 2.f*(w12.comp - w10.comp) + (w22.comp - w20.comp); \
            float gy = (w20.comp - w00.comp) + 2.f*(w21.comp - w01.comp) + (w22.comp - w02.comp); \
            float er = w11.comp - f0.comp; \
            c4.comp   += er*er;  ax4.comp  += gx*er;  ay4.comp  += gy*er; \
            bxx4.comp += gx*gx;  bxy4.comp += gx*gy;  byy4.comp += gy*gy; }
        DO(x) DO(y) DO(z) DO(w)
        #undef DO
    }
    float cost = (c4.x + c4.y) + (c4.z + c4.w);
    float ax   = (ax4.x + ax4.y) + (ax4.z + ax4.w);
    float ay   = (ay4.x + ay4.y) + (ay4.z + ay4.w);
    float bxx  = (bxx4.x + bxx4.y) + (bxx4.z + bxx4.w);
    float bxy  = (bxy4.x + bxy4.y) + (bxy4.z + bxy4.w);
    float byy  = (byy4.x + byy4.y) + (byy4.z + byy4.w);
    #pragma unroll
    for (int o = 16; o > 0; o >>= 1) {
        cost += __shfl_xor_sync(0xffffffffu, cost, o);
        ax   += __shfl_xor_sync(0xffffffffu, ax, o);
        ay   += __shfl_xor_sync(0xffffffffu, ay, o);
        bxx  += __shfl_xor_sync(0xffffffffu, bxx, o);
        bxy  += __shfl_xor_sync(0xffffffffu, bxy, o);
        byy  += __shfl_xor_sync(0xffffffffu, byy, o);
    }
    if (lane == 0) {
        float iz = 1.f / z1;
        float isr = 1.f / sr;
        float Jh00 = fx * iz * isr;
        float Jh02 = -fx * x1 * iz * iz * isr;
        float Jh11 = fy * iz * isr;
        float Jh12 = -fy * y1 * iz * iz * isr;
        sM[wl][0] = Jh00;  sM[wl][1] = 0.f;  sM[wl][2] = Jh02;
        sM[wl][3] = Jh02*y1;  sM[wl][4] = Jh00*z1 - Jh02*x1;  sM[wl][5] = -Jh00*y1;
        sM[wl][6] = 0.f;  sM[wl][7] = Jh11;  sM[wl][8] = Jh12;
        sM[wl][9] = Jh12*y1 - Jh11*z1;  sM[wl][10] = -Jh12*x1;  sM[wl][11] = Jh11*x1;
    }
    __syncwarp();
    float acc = 0.f;
    if (lane < 6) {
        acc = ax * sM[wl][lane] + ay * sM[wl][6+lane];
    } else if (lane < 27) {
        int q = lane - 6;
        int i = cPI[q], j = cPJ[q];
        float m0i = sM[wl][i],   m1i = sM[wl][6+i];
        float m0j = sM[wl][j],   m1j = sM[wl][6+j];
        acc = bxx*m0i*m0j + bxy*(m0i*m1j + m0j*m1i) + byy*m1i*m1j;
    } else if (lane == 27) {
        acc = cost;
    }
    if (lane < NCOMP) comb[wl][lane] = acc;
    __syncthreads();
    if (threadIdx.x < NCOMP) {
        float s = 0.f;
        #pragma unroll
        for (int w = 0; w < NWARP; w++) s += comb[w][threadIdx.x];
        g_partial[threadIdx.x * GRID_A + blockIdx.x] = s;
    }
    __syncthreads();          // CTA's g_partial store complete
    grid_dep_trigger();       // let k_solve launch while this grid drains
}

// ---------------- reduce + 6x6 LM solve + so3 exp (single block, float32 like reference) ----------
__global__ void k_solve(int iter) {
    grid_dep_wait();   // PDL: wait for k_main's g_partial
    __shared__ float red[NCOMP][8];
    __shared__ float allv[NCOMP];
    int tid = threadIdx.x;
    if (tid < NCOMP * 8) {
        int k = tid >> 3, seg = tid & 7;
        float s = 0.f;
        for (int j = 0; j < GRID_A/8; j++) s += g_partial[k*GRID_A + seg*(GRID_A/8) + j];
        red[k][seg] = s;
    }
    __syncthreads();
    if (tid < NCOMP) {
        float s = 0.f;
        #pragma unroll
        for (int j = 0; j < 8; j++) s += red[tid][j];
        allv[tid] = s;
    }
    __syncthreads();
    if (tid != 0) return;

    float g[6];
    for (int i = 0; i < 6; i++) g[i] = allv[i];
    float Hs[6][6];
    for (int q = 0; q < 21; q++) { Hs[cPI[q]][cPJ[q]] = allv[6+q]; Hs[cPJ[q]][cPI[q]] = allv[6+q]; }
    float costsum = allv[27];
    float lam = g_state[12];
    float prev = g_state[13];
    if (iter == 0) prev = costsum / (float)N_PTS;

    float A[6][7];
    for (int i = 0; i < 6; i++) {
        for (int j = 0; j < 6; j++) A[i][j] = Hs[i][j];
        A[i][i] += (Hs[i][i] + 1e-9f) * lam;
        A[i][6] = g[i];
    }
    for (int col = 0; col < 6; col++) {
        int piv = col; float best = fabsf(A[col][col]);
        for (int rr = col+1; rr < 6; rr++) if (fabsf(A[rr][col]) > best) { best = fabsf(A[rr][col]); piv = rr; }
        if (piv != col) for (int j = 0; j < 7; j++) { float tmp = A[col][j]; A[col][j] = A[piv][j]; A[piv][j] = tmp; }
        float d = A[col][col];
        for (int rr = col+1; rr < 6; rr++) {
            float f = A[rr][col] / d;
            for (int j = col; j < 7; j++) A[rr][j] -= f * A[col][j];
        }
    }
    float xs[6];
    for (int i = 5; i >= 0; i--) {
        float s = A[i][6];
        for (int j = i+1; j < 6; j++) s -= A[i][j] * xs[j];
        xs[i] = s / A[i][i];
    }
    float delta[6];
    int nanf = 0;
    for (int i = 0; i < 6; i++) { delta[i] = -xs[i]; if (isnan(delta[i])) nanf = 1; }

    float dw0 = delta[3], dw1 = delta[4], dw2 = delta[5];
    float th2 = dw0*dw0 + dw1*dw1 + dw2*dw2 + 1e-12f;
    float th = sqrtf(th2);
    float Aa = sinf(th) / th;
    float Bb = (1.0f - cosf(th)) / th2;
    float Wm[3][3] = { {0,-dw2,dw1}, {dw2,0,-dw0}, {-dw1,dw0,0} };
    float W2[3][3];
    for (int i = 0; i < 3; i++)
        for (int j = 0; j < 3; j++) {
            float s = 0;
            for (int k = 0; k < 3; k++) s += Wm[i][k]*Wm[k][j];
            W2[i][j] = s;
        }
    float dr[3][3];
    for (int i = 0; i < 3; i++)
        for (int j = 0; j < 3; j++)
            dr[i][j] = (i == j ? 1.0f : 0.0f) + Aa*Wm[i][j] + Bb*W2[i][j];

    float Rd[3][3], td[3];
    for (int i = 0; i < 3; i++) { for (int j = 0; j < 3; j++) Rd[i][j] = g_state[i*3+j]; td[i] = g_state[9+i]; }
    for (int i = 0; i < 3; i++) {
        for (int j = 0; j < 3; j++) {
            float s = 0;
            for (int k = 0; k < 3; k++) s += dr[i][k]*Rd[k][j];
            g_state[14 + i*3 + j] = s;
        }
        float s = 0;
        for (int k = 0; k < 3; k++) s += dr[i][k]*td[k];
        g_state[23+i] = s + delta[i];
    }
    g_state[26] = (float)nanf;
    g_state[13] = prev;
    grid_dep_trigger();   // candidate state written; let k_cand launch now
}

// ---------------- candidate cost evaluation ----------------
__global__ void __launch_bounds__(BLOCK_A) k_cand(const float* __restrict__ K1, const void* srp) {
    float sr = decode_sr(srp);
    int lane = threadIdx.x & 31;
    int wl   = threadIdx.x >> 5;
    int p    = blockIdx.x * NWARP + wl;
    __shared__ float s8[NWARP];

    // iteration-invariant loads before the PDL wait
    float Px = g_pts0[3*p], Py = g_pts0[3*p+1], Pz = g_pts0[3*p+2];
    float K00=K1[0],K01=K1[1],K02=K1[2],K10=K1[3],K11=K1[4],K12=K1[5],K20=K1[6],K21=K1[7],K22=K1[8];

    grid_dep_wait();   // PDL: wait for k_solve's candidate state

    float Rn[9], tn0, tn1, tn2;
    #pragma unroll
    for (int i = 0; i < 9; i++) Rn[i] = g_state[14+i];
    tn0 = g_state[23]; tn1 = g_state[24]; tn2 = g_state[25];

    float x = Px*Rn[0] + Py*Rn[1] + Pz*Rn[2] + tn0;
    float y = Px*Rn[3] + Py*Rn[4] + Pz*Rn[5] + tn1;
    float z = Px*Rn[6] + Py*Rn[7] + Pz*Rn[8] + tn2;
    float h0 = K00*x + K01*y + K02*z;
    float h1 = K10*x + K11*y + K12*z;
    float h2 = K20*x + K21*y + K22*z;
    float ih2 = 1.f / h2;
    int jx = clampi((int)floorf(h0*ih2 / sr), 0, WW-1);
    int jy = clampi((int)floorf(h1*ih2 / sr), 0, HH-1);
    const float* cen = g_qt + ((size_t)(jy+1)*WP + (jx+1)) * CH;
    const float* f0p = g_feat0 + (size_t)p * CH;
    float nc = 0.f;
    #pragma unroll
    for (int k = 0; k < 8; k++) {
        int c = lane*4 + k*128;
        float4 q4 = LD4(cen + c);
        float4 f4 = LD4(f0p + c);
        float ex = q4.x - f4.x, ey = q4.y - f4.y, ez = q4.z - f4.z, ew = q4.w - f4.w;
        nc += (ex*ex + ey*ey) + (ez*ez + ew*ew);
    }
    #pragma unroll
    for (int o = 16; o > 0; o >>= 1) nc += __shfl_xor_sync(0xffffffffu, nc, o);
    if (lane == 0) s8[wl] = nc;
    __syncthreads();
    if (threadIdx.x == 0) {
        float tot = 0.f;
        #pragma unroll
        for (int w = 0; w < NWARP; w++) tot += s8[w];
        g_ncost_part[blockIdx.x] = tot;
    }
    __syncthreads();          // CTA's g_ncost_part store complete
    grid_dep_trigger();       // let k_accept launch while this grid drains
}

// ---------------- accept / reject ----------------
__global__ void k_accept() {
    grid_dep_wait();   // PDL: wait for k_cand's g_ncost_part
    int lane = threadIdx.x;
    float s = 0.f;
    for (int j = 0; j < GRID_A/32; j++) s += g_ncost_part[lane*(GRID_A/32) + j];
    #pragma unroll
    for (int o = 16; o > 0; o >>= 1) s += __shfl_xor_sync(0xffffffffu, s, o);
    if (lane == 0) {
        float ncost = s / (float)N_PTS;
        float prev = g_state[13];
        float lam  = g_state[12];
        bool nanf  = g_state[26] != 0.f;
        bool bad   = isnan(ncost) || nanf;
        bool worse = ncost > prev;
        float lu = lam * (worse ? 10.f : 0.1f);
        lu = fminf(fmaxf(lu, 1e-6f), 100.f);
        lam = bad ? lam : lu;
        bool accept = !(worse || bad);
        if (accept) {
            #pragma unroll
            for (int i = 0; i < 9; i++) g_state[i] = g_state[14+i];
            g_state[9]  = g_state[23];
            g_state[10] = g_state[24];
            g_state[11] = g_state[25];
            g_state[13] = ncost;
        }
        g_state[12] = lam;
    }
    __syncwarp();
    grid_dep_trigger();   // committed state written; let next k_main launch
}

__global__ void k_out(float* out, int out_size) {
    int t = threadIdx.x;
    if (t < 12 && t < out_size) out[t] = g_state[t];  // R row-major then t
}

// ---------------- host launcher ----------------
extern "C" void kernel_launch(void* const* d_in, const int* in_sizes, int n_in,
                              void* d_out, int out_size) {
    const float* q   = (const float*)d_in[0];
    const float* r   = (const float*)d_in[1];
    const float* p2d = (const float*)d_in[2];
    const float* p3d = (const float*)d_in[3];
    const float* qf  = (const float*)d_in[4];
    const float* rf  = (const float*)d_in[5];
    const float* K1  = (const float*)d_in[6];
    const void*  srp = (const void*)d_in[7];
    float* out = (float*)d_out;

    cudaLaunchAttribute pss;
    pss.id = cudaLaunchAttributeProgrammaticStreamSerialization;
    pss.val.programmaticStreamSerializationAllowed = 1;

    // setup: all four kernels are mutually independent -> PSS lets them overlap
    k_init<<<1, 32>>>(q, r);
    {
        cudaLaunchConfig_t c = {};
        c.gridDim = dim3(N_PTS/256); c.blockDim = dim3(256);
        c.attrs = &pss; c.numAttrs = 1;
        cudaLaunchKernelEx(&c, k_pts0, p3d, r);
    }
    {
        cudaLaunchConfig_t c = {};
        c.gridDim = dim3(HH*WW/128, CH/32); c.blockDim = dim3(256);
        c.attrs = &pss; c.numAttrs = 1;
        cudaLaunchKernelEx(&c, k_transpose_q, qf);
    }
    {
        cudaLaunchConfig_t c = {};
        c.gridDim = dim3(N_PTS); c.blockDim = dim3(256);
        c.attrs = &pss; c.numAttrs = 1;
        cudaLaunchKernelEx(&c, k_feat0, p2d, rf, srp);
    }

    for (int it = 0; it < ITERS; it++) {
        if (it == 0) {
            // plain launch: fully serializes against ALL setup kernels
            k_main<<<GRID_A, BLOCK_A>>>(K1, srp);
        } else {
            cudaLaunchConfig_t c = {};
            c.gridDim = dim3(GRID_A); c.blockDim = dim3(BLOCK_A);
            c.attrs = &pss; c.numAttrs = 1;
            cudaLaunchKernelEx(&c, k_main, K1, srp);
        }
        {
            cudaLaunchConfig_t c = {};
            c.gridDim = dim3(1); c.blockDim = dim3(256);
            c.attrs = &pss; c.numAttrs = 1;
            cudaLaunchKernelEx(&c, k_solve, it);
        }
        {
            cudaLaunchConfig_t c = {};
            c.gridDim = dim3(GRID_A); c.blockDim = dim3(BLOCK_A);
            c.attrs = &pss; c.numAttrs = 1;
            cudaLaunchKernelEx(&c, k_cand, K1, srp);
        }
        {
            cudaLaunchConfig_t c = {};
            c.gridDim = dim3(1); c.blockDim = dim3(32);
            c.attrs = &pss; c.numAttrs = 1;
            cudaLaunchKernelEx(&c, k_accept);
        }
    }
    k_out<<<1, 32>>>(out, out_size);   // plain launch: full serialization before output
}